// round 16
// baseline (speedup 1.0000x reference)
#include <cuda_runtime.h>
#include <cuda_fp16.h>
#include <cuda_bf16.h>
#include <math.h>

// Problem dims
#define NCTA   128
#define TPB    512
#define HDIM   1024
#define BSEQ   4096
#define INDIM  512
#define OUTDIM 512

// ---------------- scratch (device globals: allocation-free) ----------------
__device__ float  g_g0x[(size_t)BSEQ * 4 * HDIM];   // x@Wih0^T + b0  (64 MB)
__device__ float  g_h1all[(size_t)BSEQ * HDIM];     // h1 history    (16 MB)
__device__ __half g_hbuf[2][2 * HDIM];              // packed [h0 | h1] fp16, dbl-buffered

struct __align__(128) GoFlag { unsigned v; unsigned pad[31]; };
__device__ GoFlag   g_go[NCTA];     // one 128B line per CTA (monotonic round)
__device__ unsigned g_arrive;       // monotonic arrival counter

__global__ void reset_bar() {
    if (threadIdx.x == 0) g_arrive = 0;
    if (threadIdx.x < NCTA) g_go[threadIdx.x].v = 0;
}

// ---- low-contention grid barrier: atomic arrival + spread go-flags --------
__device__ __forceinline__ void grid_barrier(unsigned round, int cta) {
    __syncthreads();                       // all warps' work done
    if (threadIdx.x < 32) {
        unsigned old = 0;
        if (threadIdx.x == 0) {
            asm volatile("atom.add.acq_rel.gpu.u32 %0, [%1], 1;"
                         : "=r"(old) : "l"(&g_arrive) : "memory");
        }
        old = __shfl_sync(0xffffffffu, old, 0);
        if (old == round * NCTA - 1u) {    // last arriver releases everyone
#pragma unroll
            for (int i = 0; i < 4; i++)
                asm volatile("st.release.gpu.u32 [%0], %1;"
                             :: "l"(&g_go[threadIdx.x * 4 + i].v), "r"(round) : "memory");
        }
        if (threadIdx.x == 0) {
            unsigned v;
            do {
                asm volatile("ld.acquire.gpu.u32 %0, [%1];"
                             : "=r"(v) : "l"(&g_go[cta].v) : "memory");
            } while (v < round);
        }
    }
    __syncthreads();
}

// ---------------- persistent LSTM kernel -----------------------------------
// Rows 0..31: Whh0 (h0)   32..63: Wih1 (h0)   64..95: Whh1 (h1)
// 16 warps x 6 rows. fp16 weights + fp16 h, HFMA2 chains of 4, fp32 finish.
struct __align__(16) LstmSmem {
    __half wts[96][HDIM];    // 192 KB
    uint4  h2v4[256];        // 4 KB: halves [0..1023]=h0n(t-1), [1024..2047]=h1n(t-2)
    float  red[96];
    float  b1row[32];
    float  g0s[32];
    float  c0s[8];
    float  c1s[8];
};

__device__ __forceinline__ float sigm(float x) { return 1.f / (1.f + __expf(-x)); }

template<int CNT>
__device__ __forceinline__ void do_rows(LstmSmem& S, int r0, const uint4 hf[4], int lane) {
#pragma unroll
    for (int q = 0; q < CNT; q++) {
        int r = r0 + q;
        const uint4* wv4 = reinterpret_cast<const uint4*>(S.wts[r]);
        __half2 a0 = __float2half2_rn(0.f), a1 = a0, a2 = a0, a3 = a0;
#pragma unroll
        for (int i = 0; i < 4; i++) {
            uint4 wv = wv4[i * 32 + lane];
            const __half2* w2 = reinterpret_cast<const __half2*>(&wv);
            const __half2* h2 = reinterpret_cast<const __half2*>(&hf[i]);
            a0 = __hfma2(w2[0], h2[0], a0);
            a1 = __hfma2(w2[1], h2[1], a1);
            a2 = __hfma2(w2[2], h2[2], a2);
            a3 = __hfma2(w2[3], h2[3], a3);
        }
        __half2 t = __hadd2(__hadd2(a0, a1), __hadd2(a2, a3));
        float2 f = __half22float2(t);
        float acc = f.x + f.y;
#pragma unroll
        for (int off = 16; off; off >>= 1)
            acc += __shfl_xor_sync(0xffffffffu, acc, off);
        if (lane == 0)
            S.red[r] = acc + ((r < 32) ? S.g0s[r] : 0.f);
    }
}

__device__ __forceinline__ void st_half_cg(__half* p, float v) {
    unsigned short us = __half_as_ushort(__float2half(v));
    asm volatile("st.global.cg.u16 [%0], %1;" :: "l"(p), "h"(us) : "memory");
}

__global__ __launch_bounds__(TPB, 1) void lstm_persist(
    const float* __restrict__ Whh0, const float* __restrict__ Wih1,
    const float* __restrict__ Whh1, const float* __restrict__ bih1,
    const float* __restrict__ bhh1, const float* __restrict__ h0in,
    const float* __restrict__ c0in)
{
    extern __shared__ LstmSmem S_[];
    LstmSmem& S = S_[0];
    const int tid   = threadIdx.x;
    const int lane  = tid & 31;
    const int w     = tid >> 5;        // 0..15
    const int b     = blockIdx.x;      // 0..127
    const int jbase = b * 8;

    // ---- one-time init: weights -> SMEM fp16 (vectorized) ----
    for (int idx = tid; idx < 96 * 256; idx += TPB) {
        int r  = idx >> 8;             // 0..95
        int kq = idx & 255;            // float4 index along k
        int m = r >> 5, rr = r & 31;
        int grow = ((rr >> 3) << 10) + jbase + (rr & 7);
        const float* W = (m == 0) ? Whh0 : ((m == 1) ? Wih1 : Whh1);
        float4 wv = *reinterpret_cast<const float4*>(&W[(size_t)grow * HDIM + kq * 4]);
        __half2 p0 = __floats2half2_rn(wv.x, wv.y);
        __half2 p1 = __floats2half2_rn(wv.z, wv.w);
        uint2 st;
        st.x = *reinterpret_cast<unsigned*>(&p0);
        st.y = *reinterpret_cast<unsigned*>(&p1);
        *reinterpret_cast<uint2*>(&S.wts[r][kq * 4]) = st;
    }
    if (tid < 32) {
        int grow = ((tid >> 3) << 10) + jbase + (tid & 7);
        S.b1row[tid] = bih1[grow] + bhh1[grow];
        S.g0s[tid]   = g_g0x[grow];            // step-0 slice (includes b0)
    }
    if (tid < 8) {
        S.c0s[tid] = c0in[jbase + tid];
        S.c1s[tid] = c0in[HDIM + jbase + tid];
    }
    if (b == 0) {
        for (int k = tid; k < 2 * HDIM; k += TPB) {
            float v = h0in[k];                 // [0..1023]=h0 init, [1024..2047]=h1 init
            st_half_cg(&g_hbuf[0][k], v);
            if (k >= HDIM) st_half_cg(&g_hbuf[1][k], v);  // h1(-1) for iter 1
        }
    }
    const int myrow = ((tid >> 3) << 10) + jbase + (tid & 7);
    grid_barrier(1u, b);

    const int r0 = w * 6;
    const bool need0 = (r0 < 64);
    const bool need1 = (r0 + 6 > 64);

    // ---- pipelined recurrence: iter t does layer0(t) and layer1(t-1) ----
    for (int t = 0; t <= BSEQ; ++t) {
        const int rb = t & 1, wb = rb ^ 1;

        // broadcast: packed fp16 [h0n(t-1) | h1n(t-2)], one uint2 per thread
        uint2 hv = __ldcg(reinterpret_cast<const uint2*>(g_hbuf[rb]) + tid);
        float gpre = 0.f;
        if (tid < 32 && t + 1 < BSEQ)
            gpre = __ldcg(&g_g0x[(size_t)(t + 1) * (4 * HDIM) + myrow]);
        reinterpret_cast<uint2*>(S.h2v4)[tid] = hv;
        __syncthreads();

        uint4 f0[4], f1[4];
        if (need0) {
#pragma unroll
            for (int i = 0; i < 4; i++) f0[i] = S.h2v4[i * 32 + lane];
        }
        if (need1) {
#pragma unroll
            for (int i = 0; i < 4; i++) f1[i] = S.h2v4[128 + i * 32 + lane];
        }
        if (!need1)      do_rows<6>(S, r0, f0, lane);
        else if (!need0) do_rows<6>(S, r0, f1, lane);
        else { do_rows<4>(S, 60, f0, lane); do_rows<2>(S, 64, f1, lane); }
        __syncthreads();

        if (tid < 8) {
            if (t < BSEQ) {            // layer0 step t
                int u = tid;
                float gi = S.red[u], gf = S.red[8 + u], gg = S.red[16 + u], go = S.red[24 + u];
                float c = sigm(gf) * S.c0s[u] + sigm(gi) * tanhf(gg);
                S.c0s[u] = c;
                float h = sigm(go) * tanhf(c);
                st_half_cg(&g_hbuf[wb][jbase + u], h);
            }
        } else if (tid < 16) {
            if (t >= 1) {              // layer1 step t-1
                int u = tid - 8;
                float gi = S.red[32 + u]      + S.red[64 + u]      + S.b1row[u];
                float gf = S.red[32 + 8 + u]  + S.red[64 + 8 + u]  + S.b1row[8 + u];
                float gg = S.red[32 + 16 + u] + S.red[64 + 16 + u] + S.b1row[16 + u];
                float go = S.red[32 + 24 + u] + S.red[64 + 24 + u] + S.b1row[24 + u];
                float c = sigm(gf) * S.c1s[u] + sigm(gi) * tanhf(gg);
                S.c1s[u] = c;
                float h = sigm(go) * tanhf(c);
                st_half_cg(&g_hbuf[wb][HDIM + jbase + u], h);
                g_h1all[(size_t)(t - 1) * HDIM + jbase + u] = h;
            }
        }
        if (tid < 32 && t + 1 < BSEQ) S.g0s[tid] = gpre;

        grid_barrier((unsigned)(t + 2), b);
    }
}

// ---------------- NT SGEMM: C[M,N] = A[M,K] * B[N,K]^T + b1[N] (+ b2[N]) ----
__global__ __launch_bounds__(256, 2) void sgemm_nt(
    const float* __restrict__ A, const float* __restrict__ B,
    const float* __restrict__ b1, const float* __restrict__ b2,
    float* __restrict__ C, int M, int N, int K)
{
    __shared__ float As[16][128];
    __shared__ float Bs[16][128];
    const int bm = blockIdx.y * 128;
    const int bn = blockIdx.x * 128;
    const int tid = threadIdx.x;
    const int lr = tid >> 2;
    const int lc = (tid & 3) * 4;
    const int ty = tid >> 4;
    const int tx = tid & 15;

    float acc[8][8];
#pragma unroll
    for (int i = 0; i < 8; i++)
#pragma unroll
        for (int j = 0; j < 8; j++) acc[i][j] = 0.f;

    for (int k0 = 0; k0 < K; k0 += 16) {
        float4 a0 = *reinterpret_cast<const float4*>(A + (size_t)(bm + lr) * K + k0 + lc);
        float4 a1 = *reinterpret_cast<const float4*>(A + (size_t)(bm + lr + 64) * K + k0 + lc);
        float4 c0 = *reinterpret_cast<const float4*>(B + (size_t)(bn + lr) * K + k0 + lc);
        float4 c1 = *reinterpret_cast<const float4*>(B + (size_t)(bn + lr + 64) * K + k0 + lc);
        __syncthreads();
        As[lc + 0][lr] = a0.x; As[lc + 1][lr] = a0.y; As[lc + 2][lr] = a0.z; As[lc + 3][lr] = a0.w;
        As[lc + 0][lr + 64] = a1.x; As[lc + 1][lr + 64] = a1.y; As[lc + 2][lr + 64] = a1.z; As[lc + 3][lr + 64] = a1.w;
        Bs[lc + 0][lr] = c0.x; Bs[lc + 1][lr] = c0.y; Bs[lc + 2][lr] = c0.z; Bs[lc + 3][lr] = c0.w;
        Bs[lc + 0][lr + 64] = c1.x; Bs[lc + 1][lr + 64] = c1.y; Bs[lc + 2][lr + 64] = c1.z; Bs[lc + 3][lr + 64] = c1.w;
        __syncthreads();
#pragma unroll
        for (int kk = 0; kk < 16; kk++) {
            float4 av0 = *reinterpret_cast<const float4*>(&As[kk][ty * 8]);
            float4 av1 = *reinterpret_cast<const float4*>(&As[kk][ty * 8 + 4]);
            float4 bv0 = *reinterpret_cast<const float4*>(&Bs[kk][tx * 8]);
            float4 bv1 = *reinterpret_cast<const float4*>(&Bs[kk][tx * 8 + 4]);
            float av[8] = {av0.x, av0.y, av0.z, av0.w, av1.x, av1.y, av1.z, av1.w};
            float bv[8] = {bv0.x, bv0.y, bv0.z, bv0.w, bv1.x, bv1.y, bv1.z, bv1.w};
#pragma unroll
            for (int i = 0; i < 8; i++)
#pragma unroll
                for (int j = 0; j < 8; j++)
                    acc[i][j] = fmaf(av[i], bv[j], acc[i][j]);
        }
    }
#pragma unroll
    for (int i = 0; i < 8; i++) {
        int row = bm + ty * 8 + i;
#pragma unroll
        for (int j = 0; j < 8; j++) {
            int col = bn + tx * 8 + j;
            float v = acc[i][j] + b1[col];
            if (b2) v += b2[col];
            C[(size_t)row * N + col] = v;
        }
    }
}

// ---------------- row softmax over OUTDIM=512 -------------------------------
__global__ __launch_bounds__(256) void softmax_rows(float* __restrict__ P)
{
    const int row = blockIdx.x;
    float* q = P + (size_t)row * OUTDIM;
    const int tid = threadIdx.x;
    float v0 = q[tid];
    float v1 = q[tid + 256];
    __shared__ float sm_[8];
    __shared__ float ss_[8];

    float m = fmaxf(v0, v1);
#pragma unroll
    for (int off = 16; off; off >>= 1)
        m = fmaxf(m, __shfl_xor_sync(0xffffffffu, m, off));
    if ((tid & 31) == 0) sm_[tid >> 5] = m;
    __syncthreads();
    if (tid == 0) {
        float t = sm_[0];
#pragma unroll
        for (int i = 1; i < 8; i++) t = fmaxf(t, sm_[i]);
        sm_[0] = t;
    }
    __syncthreads();
    m = sm_[0];

    float e0 = __expf(v0 - m), e1 = __expf(v1 - m);
    float s = e0 + e1;
#pragma unroll
    for (int off = 16; off; off >>= 1)
        s += __shfl_xor_sync(0xffffffffu, s, off);
    if ((tid & 31) == 0) ss_[tid >> 5] = s;
    __syncthreads();
    if (tid == 0) {
        float t = 0.f;
#pragma unroll
        for (int i = 0; i < 8; i++) t += ss_[i];
        ss_[0] = t;
    }
    __syncthreads();
    float inv = 1.0f / ss_[0];
    q[tid] = e0 * inv;
    q[tid + 256] = e1 * inv;
}

// ---------------- launch ----------------------------------------------------
extern "C" void kernel_launch(void* const* d_in, const int* in_sizes, int n_in,
                              void* d_out, int out_size)
{
    (void)in_sizes; (void)n_in; (void)out_size;
    const float* x    = (const float*)d_in[0];
    const float* Wih0 = (const float*)d_in[1];
    const float* Whh0 = (const float*)d_in[2];
    const float* bih0 = (const float*)d_in[3];
    const float* bhh0 = (const float*)d_in[4];
    const float* Wih1 = (const float*)d_in[5];
    const float* Whh1 = (const float*)d_in[6];
    const float* bih1 = (const float*)d_in[7];
    const float* bhh1 = (const float*)d_in[8];
    const float* h0   = (const float*)d_in[9];
    const float* c0   = (const float*)d_in[10];
    const float* fc_w = (const float*)d_in[11];
    const float* fc_b = (const float*)d_in[12];
    float* out = (float*)d_out;

    cudaFuncSetAttribute(lstm_persist, cudaFuncAttributeMaxDynamicSharedMemorySize,
                         (int)sizeof(LstmSmem));

    void* p_g0x = nullptr;
    void* p_h1  = nullptr;
    cudaGetSymbolAddress(&p_g0x, g_g0x);
    cudaGetSymbolAddress(&p_h1,  g_h1all);

    // reset barrier counter + go flags (stream-ordered before persist kernel)
    reset_bar<<<1, 128>>>();

    // prologue: g0x = x @ Wih0^T + (bih0 + bhh0)   [4096 x 4096], K=512
    {
        dim3 grid(4 * HDIM / 128, BSEQ / 128);
        sgemm_nt<<<grid, 256>>>(x, Wih0, bih0, bhh0, (float*)p_g0x,
                                BSEQ, 4 * HDIM, INDIM);
    }

    // recurrence
    lstm_persist<<<NCTA, TPB, sizeof(LstmSmem)>>>(Whh0, Wih1, Whh1, bih1, bhh1, h0, c0);

    // epilogue: logits = h1_all @ fc_w^T + fc_b    [4096 x 512], K=1024
    {
        dim3 grid(OUTDIM / 128, BSEQ / 128);
        sgemm_nt<<<grid, 256>>>((const float*)p_h1, fc_w, fc_b, nullptr, out,
                                BSEQ, OUTDIM, HDIM);
    }

    softmax_rows<<<BSEQ, 256>>>(out);
}